// round 10
// baseline (speedup 1.0000x reference)
#include <cuda_runtime.h>
#include <cuda_bf16.h>
#include <cstdint>

#define N_NODES 100000
#define N_EDGES 1600000
#define FDIM    128
#define HEADS   8
#define EPS_F   1e-12f
#define ALPHA_F 0.2f

// Static device scratch (no runtime allocation).
// g_srcsum[n*16 + j] : j<8 -> s_src[n][j] ; j>=8 -> ssum[n][j-8] (accumulated,
//                      then inverted in place). 64B row per node.
// g_dst[n*8 + j]     : s_dst[n][j] (32B row).
__device__ __align__(128) float g_srcsum[N_NODES * 16];
__device__ __align__(128) float g_dst[N_NODES * 8];

// ---------------------------------------------------------------------------
// Kernel 1: per-node scores, two warps per node (role split src/dst), two
// nodes per iteration, PLUS software pipelining: next pair's x rows are
// prefetched before the current pair's reduction -> steady-state MLP ~4/warp.
// ---------------------------------------------------------------------------
__global__ void __launch_bounds__(256) scores_kernel(
    const float* __restrict__ x,
    const float* __restrict__ aa,
    int n_nodes)
{
    const int lane  = threadIdx.x & 31;
    const int gwarp = (blockIdx.x * blockDim.x + threadIdx.x) >> 5;
    const int nwarp = (gridDim.x * blockDim.x) >> 5;
    const int role  = gwarp & 1;            // 0: src rows, 1: dst rows
    const int wnode0 = gwarp >> 1;
    const int nstep  = nwarp >> 1;

    float4 areg[8];
    const float4* aa4 = reinterpret_cast<const float4*>(aa);
    {
        const int off = role ? 32 : 0;
#pragma unroll
        for (int i = 0; i < 8; i++)
            areg[i] = __ldg(&aa4[i * 64 + off + lane]);
    }

    const bool b16 = (lane & 16) != 0;
    const bool b8  = (lane & 8)  != 0;
    const bool b4  = (lane & 4)  != 0;
    const int  v   = (lane >> 2) & 7;
    const int  sub = lane & 3;

    const float4* x4 = reinterpret_cast<const float4*>(x);

    int node = wnode0;
    float4 xvA, xvB;
    bool hasA = (node < n_nodes);
    bool hasB = (node + nstep < n_nodes);
    if (hasA) xvA = __ldg(&x4[(size_t)node * 32 + lane]);
    if (hasB) xvB = __ldg(&x4[(size_t)(node + nstep) * 32 + lane]);

    while (hasA) {
        const int nodeB = node + nstep;
        const int nnode = node + 2 * nstep;

        // Prefetch next pair (keeps 4 loads in flight during reduction).
        float4 xvA2, xvB2;
        const bool hasA2 = (nnode < n_nodes);
        const bool hasB2 = (nnode + nstep < n_nodes);
        if (hasA2) xvA2 = __ldg(&x4[(size_t)nnode * 32 + lane]);
        if (hasB2) xvB2 = __ldg(&x4[(size_t)(nnode + nstep) * 32 + lane]);

        float accA[8], accB[8];
#pragma unroll
        for (int i = 0; i < 8; i++)
            accA[i] = xvA.x * areg[i].x + xvA.y * areg[i].y
                    + xvA.z * areg[i].z + xvA.w * areg[i].w;
        if (hasB) {
#pragma unroll
            for (int i = 0; i < 8; i++)
                accB[i] = xvB.x * areg[i].x + xvB.y * areg[i].y
                        + xvB.z * areg[i].z + xvB.w * areg[i].w;
        }

#pragma unroll
        for (int i = 0; i < 4; i++) {
            float gA = b16 ? accA[i] : accA[i + 4];
            float kA = b16 ? accA[i + 4] : accA[i];
            accA[i] = kA + __shfl_xor_sync(0xffffffffu, gA, 16);
        }
        if (hasB) {
#pragma unroll
            for (int i = 0; i < 4; i++) {
                float gB = b16 ? accB[i] : accB[i + 4];
                float kB = b16 ? accB[i + 4] : accB[i];
                accB[i] = kB + __shfl_xor_sync(0xffffffffu, gB, 16);
            }
        }
#pragma unroll
        for (int i = 0; i < 2; i++) {
            float gA = b8 ? accA[i] : accA[i + 2];
            float kA = b8 ? accA[i + 2] : accA[i];
            accA[i] = kA + __shfl_xor_sync(0xffffffffu, gA, 8);
        }
        if (hasB) {
#pragma unroll
            for (int i = 0; i < 2; i++) {
                float gB = b8 ? accB[i] : accB[i + 2];
                float kB = b8 ? accB[i + 2] : accB[i];
                accB[i] = kB + __shfl_xor_sync(0xffffffffu, gB, 8);
            }
        }
        {
            float gA = b4 ? accA[0] : accA[1];
            float kA = b4 ? accA[1] : accA[0];
            accA[0] = kA + __shfl_xor_sync(0xffffffffu, gA, 4);
        }
        if (hasB) {
            float gB = b4 ? accB[0] : accB[1];
            float kB = b4 ? accB[1] : accB[0];
            accB[0] = kB + __shfl_xor_sync(0xffffffffu, gB, 4);
        }
        accA[0] += __shfl_xor_sync(0xffffffffu, accA[0], 2);
        if (hasB) accB[0] += __shfl_xor_sync(0xffffffffu, accB[0], 2);
        accA[0] += __shfl_xor_sync(0xffffffffu, accA[0], 1);
        if (hasB) accB[0] += __shfl_xor_sync(0xffffffffu, accB[0], 1);

        if (role == 0) {
            if (sub == 0) {
                g_srcsum[(size_t)node * 16 + v] = accA[0];
                if (hasB) g_srcsum[(size_t)nodeB * 16 + v] = accB[0];
            } else if (sub == 1) {
                g_srcsum[(size_t)node * 16 + 8 + v] = 0.0f;
                if (hasB) g_srcsum[(size_t)nodeB * 16 + 8 + v] = 0.0f;
            }
        } else {
            if (sub == 0) {
                g_dst[(size_t)node * 8 + v] = accA[0];
                if (hasB) g_dst[(size_t)nodeB * 8 + v] = accB[0];
            }
        }

        node = nnode;
        hasA = hasA2; hasB = hasB2;
        xvA = xvA2;   xvB = xvB2;
    }
}

// ---------------------------------------------------------------------------
// Half-edge compute: heads [4h,4h+4) of edge e -> exp values.
// ---------------------------------------------------------------------------
__device__ __forceinline__ float4 he_exp(float4 a, float4 b)
{
    float e0 = a.x + b.x, e1 = a.y + b.y, e2 = a.z + b.z, e3 = a.w + b.w;
    e0 = fmaxf(e0, ALPHA_F * e0); e1 = fmaxf(e1, ALPHA_F * e1);
    e2 = fmaxf(e2, ALPHA_F * e2); e3 = fmaxf(e3, ALPHA_F * e3);
    return make_float4(__expf(e0), __expf(e1), __expf(e2), __expf(e3));
}

// ---------------------------------------------------------------------------
// Kernel 2: segment-sum of exp(e). TWO edges per thread (e and e+half):
// all 4 scattered gathers issue before any exp/RED -> MLP 4/thread.
// ---------------------------------------------------------------------------
__global__ void __launch_bounds__(256) sum_kernel(
    const int* __restrict__ row,
    const int* __restrict__ col,
    int n_edges, int half)
{
    int t = blockIdx.x * blockDim.x + threadIdx.x;
    int e0 = t >> 1;
    int h = t & 1;
    if (e0 >= half) return;
    int e1 = e0 + half;
    bool has1 = (e1 < n_edges);

    int r0 = __ldg(row + e0);
    int c0 = __ldg(col + e0);
    int r1 = 0, c1 = 0;
    if (has1) { r1 = __ldg(row + e1); c1 = __ldg(col + e1); }

    const float4* s4 = reinterpret_cast<const float4*>(g_srcsum);
    const float4* d4 = reinterpret_cast<const float4*>(g_dst);
    float4 a0 = __ldg(&s4[(size_t)r0 * 4 + h]);
    float4 b0 = __ldg(&d4[(size_t)c0 * 2 + h]);
    float4 a1, b1;
    if (has1) {
        a1 = __ldg(&s4[(size_t)r1 * 4 + h]);
        b1 = __ldg(&d4[(size_t)c1 * 2 + h]);
    }

    float4 x0 = he_exp(a0, b0);
    float* dst0 = g_srcsum + (size_t)r0 * 16 + 8 + 4 * h;
    asm volatile("red.global.add.v4.f32 [%0], {%1,%2,%3,%4};"
                 :: "l"(dst0), "f"(x0.x), "f"(x0.y), "f"(x0.z), "f"(x0.w)
                 : "memory");
    if (has1) {
        float4 x1 = he_exp(a1, b1);
        float* dst1 = g_srcsum + (size_t)r1 * 16 + 8 + 4 * h;
        asm volatile("red.global.add.v4.f32 [%0], {%1,%2,%3,%4};"
                     :: "l"(dst1), "f"(x1.x), "f"(x1.y), "f"(x1.z), "f"(x1.w)
                     : "memory");
    }
}

// ---------------------------------------------------------------------------
// Kernel 2.5: invert the ssum half of each row: s := 1/(s + EPS).
// ---------------------------------------------------------------------------
__global__ void __launch_bounds__(256) inv_kernel(int n2)  // n2 = N_NODES*2
{
    int i = blockIdx.x * blockDim.x + threadIdx.x;
    if (i >= n2) return;
    float4* p = reinterpret_cast<float4*>(g_srcsum) + ((size_t)(i >> 1) * 4 + 2 + (i & 1));
    float4 v = *p;
    v.x = __frcp_rn(v.x + EPS_F);
    v.y = __frcp_rn(v.y + EPS_F);
    v.z = __frcp_rn(v.z + EPS_F);
    v.w = __frcp_rn(v.w + EPS_F);
    *p = v;
}

// ---------------------------------------------------------------------------
// Kernel 3: a[head][e] = exp * inv_ssum[r][head]. TWO edges per thread,
// 6 scattered gathers in flight.
// ---------------------------------------------------------------------------
__global__ void __launch_bounds__(256) out_kernel(
    const int* __restrict__ row,
    const int* __restrict__ col,
    float* __restrict__ out,
    int n_edges, int half)
{
    int t = blockIdx.x * blockDim.x + threadIdx.x;
    int e0 = t >> 1;
    int h = t & 1;
    if (e0 >= half) return;
    int e1 = e0 + half;
    bool has1 = (e1 < n_edges);

    int r0 = __ldg(row + e0);
    int c0 = __ldg(col + e0);
    int r1 = 0, c1 = 0;
    if (has1) { r1 = __ldg(row + e1); c1 = __ldg(col + e1); }

    const float4* s4 = reinterpret_cast<const float4*>(g_srcsum);
    const float4* d4 = reinterpret_cast<const float4*>(g_dst);
    float4 a0 = __ldg(&s4[(size_t)r0 * 4 + h]);
    float4 s0 = __ldg(&s4[(size_t)r0 * 4 + 2 + h]);
    float4 b0 = __ldg(&d4[(size_t)c0 * 2 + h]);
    float4 a1, s1, b1;
    if (has1) {
        a1 = __ldg(&s4[(size_t)r1 * 4 + h]);
        s1 = __ldg(&s4[(size_t)r1 * 4 + 2 + h]);
        b1 = __ldg(&d4[(size_t)c1 * 2 + h]);
    }

    size_t E = (size_t)n_edges;
    {
        float4 x0 = he_exp(a0, b0);
        float* o = out + (size_t)(4 * h) * E + e0;
        o[0 * E] = x0.x * s0.x;
        o[1 * E] = x0.y * s0.y;
        o[2 * E] = x0.z * s0.z;
        o[3 * E] = x0.w * s0.w;
    }
    if (has1) {
        float4 x1 = he_exp(a1, b1);
        float* o = out + (size_t)(4 * h) * E + e1;
        o[0 * E] = x1.x * s1.x;
        o[1 * E] = x1.y * s1.y;
        o[2 * E] = x1.z * s1.z;
        o[3 * E] = x1.w * s1.w;
    }
}

extern "C" void kernel_launch(void* const* d_in, const int* in_sizes, int n_in,
                              void* d_out, int out_size)
{
    const float* x   = (const float*)d_in[0];
    const int*   row = (const int*)  d_in[1];
    const int*   col = (const int*)  d_in[2];
    const float* aa  = (const float*)d_in[3];
    float* out = (float*)d_out;

    int n_nodes = in_sizes[0] / FDIM;   // 100000
    int n_edges = in_sizes[1];          // 1600000
    int half = (n_edges + 1) / 2;

    scores_kernel<<<592, 256>>>(x, aa, n_nodes);

    int nthreads = 2 * half;            // 2 threads per edge-pair slot
    sum_kernel<<<(nthreads + 255) / 256, 256>>>(row, col, n_edges, half);
    {
        int n2 = n_nodes * 2;
        inv_kernel<<<(n2 + 255) / 256, 256>>>(n2);
    }
    out_kernel<<<(nthreads + 255) / 256, 256>>>(row, col, out, n_edges, half);
}